// round 9
// baseline (speedup 1.0000x reference)
#include <cuda_runtime.h>

// NeuralODE: 100 Euler steps of y' = f(y), f(y) = sum_j w2_j*tanh(w1_j*y+b1_j)+b2.
//
// R9: two-level composed table.
//   dense : ND intervals over [-MD, MD]  (data region, h = 3.2e-4)
//   sparse: NS intervals over [-MC, MC]  (outlier safety; G_100 ~affine there)
//   k_fnode: H*f at NF+1 fine nodes (8 lanes/node)
//   k_gnode: D(x0)=G_100(x0)-x0 at all dense+sparse nodes via smem fine table;
//            writes aligned (D_i, D_{i+1}) float2 pairs
//   k_apply: per element ONE aligned LDG.64 gather + lerp (dense table L1-hot)

#define H_STEP  0.01f
#define NSTEPS  100
#define HID     50
#define NF      6144            // fine intervals; float2 smem table = 48KB
#define ND      32768           // dense composed intervals over [-MD, MD]
#define MD      5.25f
#define MDTEST  5.24f
#define NS      8192            // sparse composed intervals over [-MC, MC]
#define MC      10.5f
#define MAGIC   8388608.0f      // 2^23 round-to-int trick
#define TPB     256

__device__ float  g_fnode[NF + 1];
__device__ float2 g_dpair[ND + 1];   // dense  (D_i, D_{i+1})
__device__ float2 g_spair[NS + 1];   // sparse (D_i, D_{i+1})
__device__ float  g_fparams[2];      // {MF, invhF}

__device__ __forceinline__ float fast_tanh(float x) {
    float a = fabsf(x);
    float e = __expf(-2.0f * a);
    float t = __fdividef(1.0f - e, 1.0f + e);
    return copysignf(t, x);
}

// ---------------- pass 1: fine table of H*f, 8 lanes per node ----------------
__global__ void __launch_bounds__(TPB)
k_fnode(const float* __restrict__ w1, const float* __restrict__ b1,
        const float* __restrict__ w2, const float* __restrict__ b2) {
    int t = blockIdx.x * TPB + threadIdx.x;
    int node = t >> 3, p = t & 7;
    if (node > NF) return;

    // fsup = |b2| + sum|w2| via warp-redundant reduce
    int lane = threadIdx.x & 31;
    float s = (lane < HID) ? fabsf(__ldg(&w2[lane])) : 0.0f;
    if (lane + 32 < HID) s += fabsf(__ldg(&w2[lane + 32]));
#pragma unroll
    for (int o = 16; o; o >>= 1) s += __shfl_xor_sync(0xffffffffu, s, o);
    const float b2v  = __ldg(&b2[0]);
    const float fsup = s + fabsf(b2v);

    const float MF = MC + fsup + 2.0f;         // trajectory range + margin
    const float hF = (2.0f * MF) / (float)NF;
    if (t == 0) { g_fparams[0] = MF; g_fparams[1] = 1.0f / hF; }

    float x0 = fmaf((float)node, hF, -MF);
    float acc = 0.0f;
    int j0 = p * 7, j1 = j0 + 7; if (j1 > HID) j1 = HID;
    for (int j = j0; j < j1; j++)
        acc += __ldg(&w2[j]) * fast_tanh(fmaf(x0, __ldg(&w1[j]), __ldg(&b1[j])));
    acc += __shfl_xor_sync(0xffffffffu, acc, 4);
    acc += __shfl_xor_sync(0xffffffffu, acc, 2);
    acc += __shfl_xor_sync(0xffffffffu, acc, 1);
    if (p == 0) g_fnode[node] = H_STEP * (acc + b2v);
}

// ---------------- pass 2: 100-step map at dense + sparse nodes ----------------
__global__ void __launch_bounds__(TPB)
k_gnode() {
    __shared__ float2 tab[NF];                 // (f_i, f_{i+1}-f_i): 48KB

    // everything independent of k_fnode happens BEFORE the dependency sync
    const int   t      = blockIdx.x * TPB + threadIdx.x;
    const bool  dense  = (t <= ND);
    const int   j      = dense ? t : (t - (ND + 1));   // node idx in its table
    const float hD     = 2.0f * MD / (float)ND;
    const float hS     = 2.0f * MC / (float)NS;
    const float x0     = dense ? fmaf((float)j, hD, -MD)
                               : fmaf((float)j, hS, -MC);

    cudaGridDependencySynchronize();           // PDL: wait for k_fnode writes

    for (int i = threadIdx.x; i < NF; i += TPB) {
        float f0 = g_fnode[i];
        float f1 = g_fnode[i + 1];
        tab[i] = make_float2(f0, f1 - f0);
    }
    float MF   = g_fparams[0];
    float invh = g_fparams[1];
    __syncthreads();

    if (t > ND + 1 + NS) return;

    const float offsF = MF * invh - 0.5f;      // floor indexing via round(u-0.5)
    float y = x0;
#pragma unroll 10
    for (int st = 0; st < NSTEPS; st++) {
        float v  = fmaf(y, invh, offsF);
        float vb = v + MAGIC;
        int   iu = __float_as_int(vb) & 0x1FFF; // floor(u), NF < 8192
        float fi = vb - MAGIC;
        float tt = (v - fi) + 0.5f;             // frac in [0,1]
        float2 c = tab[iu];
        y = fmaf(c.y, tt, y + c.x);             // y += H*f_interp(y)
    }
    float D = y - x0;
    if (dense) {
        g_dpair[j].x = D;                       // pair layout: one aligned
        if (j > 0) g_dpair[j - 1].y = D;        // LDG.64 serves the gather
    } else {
        g_spair[j].x = D;
        if (j > 0) g_spair[j - 1].y = D;
    }
}

// ---------------- pass 3: apply, one LDG.64 gather per element ----------------
__global__ void __launch_bounds__(TPB)
k_apply(const float* __restrict__ x, float* __restrict__ out, int B) {
    const float invhD = (float)ND / (2.0f * MD);
    const float offsD = MD * invhD - 0.5f;     // floor via round(u-0.5)
    const float invhS = (float)NS / (2.0f * MC);
    const float offsS = MC * invhS - 0.5f;
    const float vmaxS = (float)NS - 1.001f;

    int nvec = B >> 2;
    int i = blockIdx.x * TPB + threadIdx.x;

    if (i < nvec) {
        // issue x load BEFORE the dependency sync: overlaps with k_gnode
        float4 v4 = reinterpret_cast<const float4*>(x)[i];
        cudaGridDependencySynchronize();

        float r[4] = {v4.x, v4.y, v4.z, v4.w};
#pragma unroll
        for (int k = 0; k < 4; k++) {
            float y = r[k];
            float2 c;
            float  t;
            if (fabsf(y) < MDTEST) {           // data region (virtually always)
                float v  = fmaf(y, invhD, offsD);
                float vb = v + MAGIC;
                int   iu = __float_as_int(vb) & 0xFFFF;  // ND = 32768
                float fi = vb - MAGIC;
                t = (v - fi) + 0.5f;
                c = __ldg(&g_dpair[iu]);
            } else {                            // outlier safety net
                float v = fmaf(y, invhS, offsS);
                v = fminf(fmaxf(v, 0.0f), vmaxS);
                float vb = v + MAGIC;
                int   iu = __float_as_int(vb) & 0x3FFF;  // NS = 8192
                float fi = vb - MAGIC;
                t = (v - fi) + 0.5f;
                c = __ldg(&g_spair[iu]);
            }
            r[k] = y + fmaf(c.y - c.x, t, c.x);
        }
        reinterpret_cast<float4*>(out)[i] = make_float4(r[0], r[1], r[2], r[3]);
    } else {
        cudaGridDependencySynchronize();
    }

    // scalar tail (B not divisible by 4)
    int tail = B & 3;
    int g = blockIdx.x * TPB + threadIdx.x;
    if (g < tail) {
        int e = (B & ~3) + g;
        float y = x[e];
        float v = fmaf(y, invhS, offsS);
        v = fminf(fmaxf(v, 0.0f), vmaxS);
        float vb = v + MAGIC;
        int   iu = __float_as_int(vb) & 0x3FFF;
        float fi = vb - MAGIC;
        float t  = (v - fi) + 0.5f;
        float2 c = __ldg(&g_spair[iu]);
        out[e] = y + fmaf(c.y - c.x, t, c.x);
    }
}

// ---------------- launch (PDL on the two consumers) ----------------
template <typename... Args>
static void launch_pdl(void (*kern)(Args...), int grid, bool pdl, Args... args) {
    cudaLaunchConfig_t cfg = {};
    cfg.gridDim  = dim3(grid, 1, 1);
    cfg.blockDim = dim3(TPB, 1, 1);
    cfg.stream   = 0;
    cudaLaunchAttribute attr[1];
    attr[0].id = cudaLaunchAttributeProgrammaticStreamSerialization;
    attr[0].val.programmaticStreamSerializationAllowed = 1;
    cfg.attrs    = pdl ? attr : nullptr;
    cfg.numAttrs = pdl ? 1 : 0;
    cudaLaunchKernelEx(&cfg, kern, args...);
}

extern "C" void kernel_launch(void* const* d_in, const int* in_sizes, int n_in,
                              void* d_out, int out_size) {
    const float* x  = (const float*)d_in[0];
    const float* w1 = (const float*)d_in[1];
    const float* b1 = (const float*)d_in[2];
    const float* w2 = (const float*)d_in[3];
    const float* b2 = (const float*)d_in[4];
    int B = in_sizes[0];

    int thrA = (NF + 1) * 8;
    launch_pdl(k_fnode, (thrA + TPB - 1) / TPB, false, w1, b1, w2, b2);

    int totalB = (ND + 1) + (NS + 1);
    launch_pdl(k_gnode, (totalB + TPB - 1) / TPB, true);

    int nvec = (B + 3) / 4;
    launch_pdl(k_apply, (nvec + TPB - 1) / TPB, true,
               x, (float*)d_out, B);
}